// round 15
// baseline (speedup 1.0000x reference)
#include <cuda_runtime.h>
#include <cuda_fp16.h>
#include <cstdint>
#include <cstddef>

#define DINL __device__ __forceinline__

// ------------------------- problem sizes -------------------------
#define NN 8192
#define KK 2048
#define DD 512
#define NH (NN - KK)   // 6144

// ------------------------- scratch (static device globals) -------------------------
__device__ __half g_xf [NN*DD];
__device__ __half g_s0f[NN*KK];
__device__ __half g_s1f[KK*NN];
__device__ __half g_s2f[(size_t)NN*NH];
__device__ __half g_s3f[(size_t)NH*NN];
__device__ __half g_Wth[DD*DD];
__device__ __half g_Pth[DD*NN];
__device__ __half g_T1h[DD*KK];
__device__ __half g_T3h[DD*NH];
__device__ float g_T1p[4*KK*DD];
__device__ float g_T3p[3*NH*DD];
__device__ float g_OL [NN*DD];

// ------------------------- ptx helpers (base ISA only) ----
DINL uint32_t smem_u32(const void* p) {
    uint32_t a;
    asm("{ .reg .u64 t; cvta.to.shared.u64 t, %1; cvt.u32.u64 %0, t; }" : "=r"(a) : "l"(p));
    return a;
}
DINL void cp16(uint32_t saddr, const void* g) {
    asm volatile("cp.async.cg.shared.global [%0], [%1], 16;" :: "r"(saddr), "l"(g));
}
DINL void cp_commit() { asm volatile("cp.async.commit_group;" ::: "memory"); }
DINL void cp_wait1()  { asm volatile("cp.async.wait_group 1;" ::: "memory"); }
DINL void cp_wait0()  { asm volatile("cp.async.wait_group 0;" ::: "memory"); }

DINL void ldsm4(uint32_t (&r)[4], uint32_t addr) {
    asm volatile("ldmatrix.sync.aligned.m8n8.x4.shared.b16 {%0,%1,%2,%3}, [%4];"
                 : "=r"(r[0]), "=r"(r[1]), "=r"(r[2]), "=r"(r[3]) : "r"(addr));
}
DINL void mma_f16(float (&d)[4], const uint32_t (&a)[4], const uint32_t* b) {
    asm volatile(
        "mma.sync.aligned.m16n8k16.row.col.f32.f16.f16.f32 "
        "{%0,%1,%2,%3}, {%4,%5,%6,%7}, {%8,%9}, {%0,%1,%2,%3};"
        : "+f"(d[0]), "+f"(d[1]), "+f"(d[2]), "+f"(d[3])
        : "r"(a[0]), "r"(a[1]), "r"(a[2]), "r"(a[3]), "r"(b[0]), "r"(b[1]));
}

// ------------------------- GEMM -------------------------
// C[z][M,512] = A[M,K] @ Bt^T, A single fp16; Bt fp16 hi(/lo) — NPASS∈{1,2}.
// TRANSP: skip fp32 C; write fp16 transposed output Ct[512, M] via smem staging.
// CTA tile 256x128, BK=64 (128B SW128 rows), 8 warps of 64x64, 2-stage cp.async.
static constexpr int OFF_A  = 0;       // 32 KB (256 rows x 128B)
static constexpr int OFF_BH = 32768;   // 16 KB
static constexpr int OFF_BL = 49152;   // 16 KB (NPASS==2 only)

template <int NPASS> struct StageCfg {
    static constexpr int STAGE = (NPASS == 2) ? 65536 : 49152;
    static constexpr int SMEM  = 2 * STAGE;
};

DINL void ld_sec(uint32_t sdst, const char* src, int row0, size_t pitch,
                 size_t kbyte, int nIter, int tid)
{
    for (int i = 0; i < nIter; i++) {
        int idx = tid * 16 + i * 4096;
        int row = idx >> 7, col = idx & 127;
        uint32_t sw = (uint32_t)idx ^ (((uint32_t)idx >> 3) & 0x70);
        cp16(sdst + sw, src + (size_t)(row0 + row) * pitch + kbyte + col);
    }
}

template <bool FINAL, int NPASS, bool TRANSP>
__global__ void __launch_bounds__(256, 1)
hgemm(const __half* __restrict__ A_,
      const __half* __restrict__ Bh_, const __half* __restrict__ Bl_,
      float* __restrict__ C, __half* __restrict__ Ct, int M, int K,
      const float* __restrict__ other, const float* __restrict__ bias)
{
    constexpr int STAGE_BYTES = StageCfg<NPASS>::STAGE;
    extern __shared__ char smem[];
    const uint32_t sb0 = smem_u32(smem);
    const int tid = threadIdx.x, wid = tid >> 5, lane = tid & 31;
    const int brow = blockIdx.y * 256, bcol = blockIdx.x * 128;
    const int warpM = (wid & 3) * 64, warpN = (wid >> 2) * 64;

    const int kchunks = K >> 6;
    const int Z = gridDim.z, z = blockIdx.z;
    const int kc0 = (int)(((long long)kchunks * z) / Z);
    const int kc1 = (int)(((long long)kchunks * (z + 1)) / Z);
    const int total = kc1 - kc0;
    float* Cz = C + (size_t)z * M * 512;

    const char* A  = (const char*)A_;
    const char* Bh = (const char*)Bh_;
    const char* Bl = (const char*)Bl_;
    const size_t pitch = (size_t)K * 2;

    const uint32_t xorv = (uint32_t)(lane & 7) << 4;
    const uint32_t kaA = ((lane >> 4) & 1) * 16;
    const uint32_t kbB = ((lane >> 3) & 1) * 16;
    uint32_t aRowOff[4], bRowOff[4];
#pragma unroll
    for (int am = 0; am < 4; am++)
        aRowOff[am] = (uint32_t)(warpM + am * 16 + (lane & 15)) * 128;
#pragma unroll
    for (int bg = 0; bg < 4; bg++)
        bRowOff[bg] = (uint32_t)(warpN + bg * 16 + ((lane >> 4) & 1) * 8 + (lane & 7)) * 128;

    float acc[4][8][4];
#pragma unroll
    for (int i = 0; i < 4; i++)
#pragma unroll
        for (int j = 0; j < 8; j++)
#pragma unroll
            for (int t = 0; t < 4; t++) acc[i][j][t] = 0.0f;

    // pipeline prologue: fill both stages
#pragma unroll 1
    for (int p = 0; p < 2; p++) {
        uint32_t sb = sb0 + p * STAGE_BYTES;
        size_t kb = (size_t)(kc0 + p) * 128;
        ld_sec(sb + OFF_A,  A,  brow, pitch, kb, 8, tid);
        ld_sec(sb + OFF_BH, Bh, bcol, pitch, kb, 4, tid);
        if (NPASS == 2) ld_sec(sb + OFF_BL, Bl, bcol, pitch, kb, 4, tid);
        cp_commit();
    }

#pragma unroll 1
    for (int it = 0; it < total; ++it) {
        const int s = it & 1;
        if (it < total - 1) cp_wait1(); else cp_wait0();
        __syncthreads();

        const uint32_t sb = sb0 + s * STAGE_BYTES;
#pragma unroll 1
        for (int ks = 0; ks < 4; ks++) {
            const uint32_t kA = ((uint32_t)(ks * 32) + kaA) ^ xorv;
            const uint32_t kB = ((uint32_t)(ks * 32) + kbB) ^ xorv;
            uint32_t ah[4][4];
#pragma unroll
            for (int am = 0; am < 4; am++)
                ldsm4(ah[am], sb + OFF_A + aRowOff[am] + kA);
#pragma unroll
            for (int bg = 0; bg < 4; bg++) {
                uint32_t bh[4], bl[4];
                ldsm4(bh, sb + OFF_BH + bRowOff[bg] + kB);
                if (NPASS == 2) ldsm4(bl, sb + OFF_BL + bRowOff[bg] + kB);
#pragma unroll
                for (int am = 0; am < 4; am++)
#pragma unroll
                    for (int h = 0; h < 2; h++)
                        mma_f16(acc[am][bg * 2 + h], ah[am], bh + h * 2);
                if (NPASS == 2) {
#pragma unroll
                    for (int am = 0; am < 4; am++)
#pragma unroll
                        for (int h = 0; h < 2; h++)
                            mma_f16(acc[am][bg * 2 + h], ah[am], bl + h * 2);
                }
            }
        }
        __syncthreads();
        const int nx = it + 2;
        if (nx < total) {
            size_t kb = (size_t)(kc0 + nx) * 128;
            ld_sec(sb + OFF_A,  A,  brow, pitch, kb, 8, tid);
            ld_sec(sb + OFF_BH, Bh, bcol, pitch, kb, 4, tid);
            if (NPASS == 2) ld_sec(sb + OFF_BL, Bl, bcol, pitch, kb, 4, tid);
            cp_commit();
        }
    }

    if (TRANSP) {
        // Fused transpose + fp16 epilogue via smem staging (stride 264 halfs).
        __syncthreads();                 // all warps done reading stage smem
        __half* tr = (__half*)smem;
#pragma unroll
        for (int am = 0; am < 4; am++) {
#pragma unroll
            for (int bn = 0; bn < 8; bn++) {
                const int r0 = warpM + am * 16 + (lane >> 2);
                const int c0 = warpN + bn * 8 + (lane & 3) * 2;
#pragma unroll
                for (int h = 0; h < 2; h++) {
                    const int r = r0 + h * 8;
                    tr[(c0    ) * 264 + r] = __float2half_rn(acc[am][bn][h * 2]);
                    tr[(c0 + 1) * 264 + r] = __float2half_rn(acc[am][bn][h * 2 + 1]);
                }
            }
        }
        __syncthreads();
        const int c = tid >> 1, j0 = (tid & 1) * 128;
        __half* gdst = Ct + (size_t)(bcol + c) * M + brow + j0;
        const __half* srow = tr + c * 264 + j0;
#pragma unroll
        for (int t = 0; t < 16; t++)
            *(uint4*)(gdst + t * 8) = *(const uint4*)(srow + t * 8);
        return;
    }

    // standard epilogue
#pragma unroll
    for (int am = 0; am < 4; am++) {
#pragma unroll
        for (int bn = 0; bn < 8; bn++) {
            const int r0 = brow + warpM + am * 16 + (lane >> 2);
            const int cg = bcol + warpN + bn * 8 + (lane & 3) * 2;
#pragma unroll
            for (int h = 0; h < 2; h++) {
                const int row = r0 + h * 8;
                float2 v = make_float2(acc[am][bn][h * 2], acc[am][bn][h * 2 + 1]);
                size_t o = (size_t)row * 512 + cg;
                if (FINAL) {
                    float2 ov = *(const float2*)(other + o);
                    float2 bb = *(const float2*)(bias + cg);
                    v.x = fmaxf(fmaxf(v.x, ov.x) + bb.x, 0.0f);
                    v.y = fmaxf(fmaxf(v.y, ov.y) + bb.y, 0.0f);
                }
                *(float2*)(Cz + o) = v;
            }
        }
    }
}

// --------- convert fp32 -> fp16, 128-thread blocks (co-residency with hgemm) ---------
__global__ void __launch_bounds__(128)
cvtA(const float* __restrict__ src, __half* __restrict__ dst, size_t n4)
{
    size_t stride = (size_t)gridDim.x * blockDim.x;
    for (size_t i = (size_t)blockIdx.x * blockDim.x + threadIdx.x; i < n4; i += stride) {
        float4 v = ((const float4*)src)[i];
        __half2 p0 = __floats2half2_rn(v.x, v.y);
        __half2 p1 = __floats2half2_rn(v.z, v.w);
        uint2 o;
        o.x = *(const uint32_t*)&p0;
        o.y = *(const uint32_t*)&p1;
        ((uint2*)dst)[i] = o;
    }
}

// ------------- combine(split-K) + scale + transpose + fp16 (hi, optional lo) -------------
__global__ void cst(const float* __restrict__ parts, int Z, int Min,
                    __half* __restrict__ th, __half* __restrict__ tl,
                    const float* __restrict__ alpha, int aidx)
{
    __shared__ float tile[32][33];
    const int m0 = blockIdx.x * 32, n0 = blockIdx.y * 32;
    const int tx = threadIdx.x, ty = threadIdx.y;   // 32 x 8
    float s = 1.0f;
    if (aidx >= 0) {
        float e0 = __expf(alpha[0]), e1 = __expf(alpha[1]);
        s = (aidx == 0 ? e0 : e1) / (e0 + e1);
    }
#pragma unroll
    for (int j = 0; j < 32; j += 8) {
        int m = m0 + ty + j;
        float acc = 0.0f;
        for (int zz = 0; zz < Z; zz++)
            acc += parts[((size_t)zz * Min + m) * 512 + n0 + tx];
        tile[ty + j][tx] = acc * s;
    }
    __syncthreads();
#pragma unroll
    for (int j = 0; j < 32; j += 8) {
        float v = tile[tx][ty + j];
        __half h = __float2half_rn(v);
        size_t o = (size_t)(n0 + ty + j) * Min + m0 + tx;
        th[o] = h;
        if (tl) tl[o] = __float2half_rn(v - __half2float(h));
    }
}

// ------------------------- host -------------------------
extern "C" void kernel_launch(void* const* d_in, const int* in_sizes, int n_in,
                              void* d_out, int out_size)
{
    const float* x     = (const float*)d_in[0];
    const float* w     = (const float*)d_in[1];
    const float* alpha = (const float*)d_in[2];
    const float* bias  = (const float*)d_in[3];
    const float* s0    = (const float*)d_in[4];
    const float* s1    = (const float*)d_in[5];
    const float* s2    = (const float*)d_in[6];
    const float* s3    = (const float*)d_in[7];
    float* out = (float*)d_out;

    __half *xf, *s0f, *s1f, *s2f, *s3f;
    __half *Wth, *Pth, *T1h, *T3h;
    float *pT1p, *pT3p, *pOL;
    cudaGetSymbolAddress((void**)&xf,  g_xf);
    cudaGetSymbolAddress((void**)&s0f, g_s0f);
    cudaGetSymbolAddress((void**)&s1f, g_s1f);
    cudaGetSymbolAddress((void**)&s2f, g_s2f);
    cudaGetSymbolAddress((void**)&s3f, g_s3f);
    cudaGetSymbolAddress((void**)&Wth, g_Wth);
    cudaGetSymbolAddress((void**)&Pth, g_Pth);
    cudaGetSymbolAddress((void**)&T1h, g_T1h);
    cudaGetSymbolAddress((void**)&T3h, g_T3h);
    cudaGetSymbolAddress((void**)&pT1p, g_T1p);
    cudaGetSymbolAddress((void**)&pT3p, g_T3p); cudaGetSymbolAddress((void**)&pOL, g_OL);

    cudaFuncSetAttribute((const void*)hgemm<false, 1, true>,
                         cudaFuncAttributeMaxDynamicSharedMemorySize, StageCfg<1>::SMEM);
    cudaFuncSetAttribute((const void*)hgemm<false, 1, false>,
                         cudaFuncAttributeMaxDynamicSharedMemorySize, StageCfg<1>::SMEM);
    cudaFuncSetAttribute((const void*)hgemm<true, 1, false>,
                         cudaFuncAttributeMaxDynamicSharedMemorySize, StageCfg<1>::SMEM);

    // One-time host-resource creation (first call = uncaptured correctness run).
    static cudaStream_t side = nullptr, side2 = nullptr;
    static cudaEvent_t evRoot, evS3, evS1, evS0, evS2, evP, evG3;
    if (!side) {
        int prLo, prHi;   // prHi = numerically-lowest value = highest priority
        cudaDeviceGetStreamPriorityRange(&prLo, &prHi);
        cudaStreamCreateWithPriority(&side,  cudaStreamNonBlocking, prLo);  // low prio
        cudaStreamCreateWithPriority(&side2, cudaStreamNonBlocking, prHi);  // high prio
        cudaEventCreateWithFlags(&evRoot, cudaEventDisableTiming);
        cudaEventCreateWithFlags(&evS3,   cudaEventDisableTiming);
        cudaEventCreateWithFlags(&evS1,   cudaEventDisableTiming);
        cudaEventCreateWithFlags(&evS0,   cudaEventDisableTiming);
        cudaEventCreateWithFlags(&evS2,   cudaEventDisableTiming);
        cudaEventCreateWithFlags(&evP,    cudaEventDisableTiming);
        cudaEventCreateWithFlags(&evG3,   cudaEventDisableTiming);
    }

    // ---- fork: low-priority side stream converts the s-matrices (128-thr CTAs
    //      sized to co-reside with hgemm's register leftover) ----
    cudaEventRecord(evRoot, 0);
    cudaStreamWaitEvent(side, evRoot, 0);
    cvtA<<<2368, 128, 0, side>>>(s3, s3f, (size_t)NH * NN / 4);  cudaEventRecord(evS3, side);
    cvtA<<<1184, 128, 0, side>>>(s1, s1f, (size_t)KK * NN / 4);  cudaEventRecord(evS1, side);
    cvtA<<<1184, 128, 0, side>>>(s0, s0f, (size_t)NN * KK / 4);  cudaEventRecord(evS0, side);
    cvtA<<<2368, 128, 0, side>>>(s2, s2f, (size_t)NN * NH / 4);  cudaEventRecord(evS2, side);

    // ---- main stream: x/W prep + G1 (fused transposed epilogue -> Pth) ----
    cvtA<<<592, 128>>>(x, xf, (size_t)NN * DD / 4);
    cst<<<dim3(DD / 32, 16), dim3(32, 8)>>>(w, 1, DD, Wth, nullptr, alpha, -1);
    // G1: Pth = (x @ W)^T fp16   [512,8192], K=512, 1-pass B, fused transpose
    hgemm<false, 1, true><<<dim3(4, 32, 1), 256, StageCfg<1>::SMEM>>>(
        xf, Wth, nullptr, nullptr, Pth, NN, DD, nullptr, nullptr);
    cudaEventRecord(evP, 0);

    // ---- chain B (side2, high prio): G2 -> cstT1 -> G3 (produces OL) ----
    cudaStreamWaitEvent(side2, evP, 0);
    cudaStreamWaitEvent(side2, evS1, 0);
    // G2: T1 = s1 @ P      [2048,512], K=8192, split-K=4, 1-pass B
    hgemm<false, 1, false><<<dim3(4, 8, 4), 256, StageCfg<1>::SMEM, side2>>>(
        s1f, Pth, nullptr, pT1p, nullptr, KK, NN, nullptr, nullptr);
    cst<<<dim3(KK / 32, 16), dim3(32, 8), 0, side2>>>(pT1p, 4, KK, T1h, nullptr, alpha, 0);
    cudaStreamWaitEvent(side2, evS0, 0);
    // G3: OL = s0 @ T1     [8192,512], K=2048, 1-pass B
    hgemm<false, 1, false><<<dim3(4, 32, 1), 256, StageCfg<1>::SMEM, side2>>>(
        s0f, T1h, nullptr, pOL, nullptr, NN, KK, nullptr, nullptr);
    cudaEventRecord(evG3, side2);

    // ---- chain A (main): G4 -> cstT3 ----
    cudaStreamWaitEvent(0, evS3, 0);
    // G4: T3 = s3 @ P      [6144,512], K=8192, split-K=3, 1-pass B
    hgemm<false, 1, false><<<dim3(4, 24, 3), 256, StageCfg<1>::SMEM>>>(
        s3f, Pth, nullptr, pT3p, nullptr, NH, NN, nullptr, nullptr);
    cst<<<dim3(NH / 32, 16), dim3(32, 8)>>>(pT3p, 3, NH, T3h, nullptr, alpha, 1);

    // ---- join: G5 needs T3h (main), OL (side2), s2f (side) ----
    cudaStreamWaitEvent(0, evG3, 0);
    cudaStreamWaitEvent(0, evS2, 0);
    // G5: out = relu(max(OL, s2 @ T3) + bias)   [8192,512], K=6144, 1-pass B
    hgemm<true, 1, false><<<dim3(4, 32, 1), 256, StageCfg<1>::SMEM>>>(
        s2f, T3h, nullptr, out, nullptr, NN, NH, pOL, bias);
}